// round 4
// baseline (speedup 1.0000x reference)
#include <cuda_runtime.h>

#define Bsz 2
#define Sq  2048
#define Dm  1024
#define Hn  16
#define HD  64
#define BH  (Bsz*Hn)                 // 32
#define TOK (Bsz*Sq)                 // 4096
#define OUT_ATTN ((long long)Bsz*Sq*Dm)

typedef unsigned long long u64;

// ---------------------------------------------------------------------------
// Scratch
// ---------------------------------------------------------------------------
__device__ float g_Q[TOK * Dm];
__device__ float g_K[TOK * Dm];
__device__ float g_V[TOK * Dm];
__device__ float g_O[TOK * Dm];

// ---------------------------------------------------------------------------
// f32x2 packed helpers (sm_100+)
// ---------------------------------------------------------------------------
__device__ __forceinline__ u64 pack2(float x, float y) {
    u64 r; asm("mov.b64 %0, {%1, %2};" : "=l"(r) : "f"(x), "f"(y)); return r;
}
__device__ __forceinline__ void ffma2(u64& d, u64 a, u64 b) {
    asm("fma.rn.f32x2 %0, %1, %2, %0;" : "+l"(d) : "l"(a), "l"(b));
}
__device__ __forceinline__ float2 unpack2(u64 v) {
    float2 r; asm("mov.b64 {%0, %1}, %2;" : "=f"(r.x), "=f"(r.y) : "l"(v)); return r;
}

// ---------------------------------------------------------------------------
// NT GEMM, double-buffered, packed-f32x2 inner loop.
// C[M,N] = alpha * A[M,K] @ B[N,K]^T. BM=BN=128, BK=16, 256 thr, 8x8/thread.
// A tile stored duplicated in smem so both MMA operands load as packed u64.
// ---------------------------------------------------------------------------
__device__ __forceinline__ void nt_compute(const float (*As)[256],
                                           const float (*Bs)[128],
                                           int ty, int tx, u64 acc[8][4])
{
#pragma unroll
    for (int kk = 0; kk < 16; kk++) {
        const ulonglong2* ap = (const ulonglong2*)&As[kk][ty * 16];
        const ulonglong2* bp = (const ulonglong2*)&Bs[kk][tx * 8];
        u64 a8[8], b4[4];
#pragma unroll
        for (int q = 0; q < 4; q++) { ulonglong2 t = ap[q]; a8[2*q] = t.x; a8[2*q+1] = t.y; }
#pragma unroll
        for (int q = 0; q < 2; q++) { ulonglong2 t = bp[q]; b4[2*q] = t.x; b4[2*q+1] = t.y; }
#pragma unroll
        for (int i = 0; i < 8; i++)
#pragma unroll
            for (int jp = 0; jp < 4; jp++) ffma2(acc[i][jp], a8[i], b4[jp]);
    }
}

__global__ __launch_bounds__(256, 2) void gemm_nt_db(
    const float* __restrict__ A, int lda, long long sAb, long long sAh,
    const float* __restrict__ Bm, int ldb, long long sBb, long long sBh,
    float* __restrict__ C, int ldc, long long sCb, long long sCh,
    int K, float alpha)
{
    const int z = blockIdx.z, zb = z >> 4, zh = z & 15;
    A  += (long long)zb * sAb + (long long)zh * sAh;
    Bm += (long long)zb * sBb + (long long)zh * sBh;
    C  += (long long)zb * sCb + (long long)zh * sCh;

    __shared__ float As[2][16][256];   // 32 KB (A duplicated along m)
    __shared__ float Bs[2][16][128];   // 16 KB

    const int tid = threadIdx.x;
    const int tx = tid & 15, ty = tid >> 4;
    const int bm = blockIdx.y * 128, bn = blockIdx.x * 128;
    const int lm = tid >> 1, lk = (tid & 1) * 8;

    const float* Aptr = A  + (long long)(bm + lm) * lda + lk;
    const float* Bptr = Bm + (long long)(bn + lm) * ldb + lk;

    u64 acc[8][4];
#pragma unroll
    for (int i = 0; i < 8; i++)
#pragma unroll
        for (int jp = 0; jp < 4; jp++) acc[i][jp] = 0ULL;

    // tile 0
    {
        float4 a0 = *(const float4*)(Aptr);
        float4 a1 = *(const float4*)(Aptr + 4);
        float4 b0 = *(const float4*)(Bptr);
        float4 b1 = *(const float4*)(Bptr + 4);
        float av[8] = {a0.x,a0.y,a0.z,a0.w,a1.x,a1.y,a1.z,a1.w};
        float bv[8] = {b0.x,b0.y,b0.z,b0.w,b1.x,b1.y,b1.z,b1.w};
#pragma unroll
        for (int j = 0; j < 8; j++) {
            *(u64*)&As[0][lk + j][2 * lm] = pack2(av[j], av[j]);
            Bs[0][lk + j][lm] = bv[j];
        }
    }
    __syncthreads();

    int buf = 0;
    for (int k0 = 16; k0 < K; k0 += 16) {
        float4 a0 = *(const float4*)(Aptr + k0);
        float4 a1 = *(const float4*)(Aptr + k0 + 4);
        float4 b0 = *(const float4*)(Bptr + k0);
        float4 b1 = *(const float4*)(Bptr + k0 + 4);

        nt_compute(As[buf], Bs[buf], ty, tx, acc);

        {
            float av[8] = {a0.x,a0.y,a0.z,a0.w,a1.x,a1.y,a1.z,a1.w};
            float bv[8] = {b0.x,b0.y,b0.z,b0.w,b1.x,b1.y,b1.z,b1.w};
            const int nb = buf ^ 1;
#pragma unroll
            for (int j = 0; j < 8; j++) {
                *(u64*)&As[nb][lk + j][2 * lm] = pack2(av[j], av[j]);
                Bs[nb][lk + j][lm] = bv[j];
            }
        }
        __syncthreads();
        buf ^= 1;
    }
    nt_compute(As[buf], Bs[buf], ty, tx, acc);

    const u64 alpha2 = pack2(alpha, alpha);
#pragma unroll
    for (int i = 0; i < 8; i++) {
        float* crow = C + (long long)(bm + ty * 8 + i) * ldc + bn + tx * 8;
#pragma unroll
        for (int jp = 0; jp < 4; jp++) {
            u64 r = 0ULL;
            asm("fma.rn.f32x2 %0, %1, %2, %0;" : "+l"(r) : "l"(acc[i][jp]), "l"(alpha2));
            float2 v = unpack2(r);
            crow[2 * jp]     = v.x;
            crow[2 * jp + 1] = v.y;
        }
    }
}

// ---------------------------------------------------------------------------
// NN GEMM (P @ V_h), double-buffered, packed-f32x2. BM=128, BN=64, BK=16.
// 256 threads, 8x4 per thread.
// ---------------------------------------------------------------------------
__device__ __forceinline__ void nn_compute(const float (*As)[256],
                                           const float (*Bs)[64],
                                           int ty, int tx, u64 acc[8][2])
{
#pragma unroll
    for (int kk = 0; kk < 16; kk++) {
        const ulonglong2* ap = (const ulonglong2*)&As[kk][ty * 16];
        const ulonglong2* bp = (const ulonglong2*)&Bs[kk][tx * 4];
        u64 a8[8], b2[2];
#pragma unroll
        for (int q = 0; q < 4; q++) { ulonglong2 t = ap[q]; a8[2*q] = t.x; a8[2*q+1] = t.y; }
        { ulonglong2 t = bp[0]; b2[0] = t.x; b2[1] = t.y; }
#pragma unroll
        for (int i = 0; i < 8; i++)
#pragma unroll
            for (int jp = 0; jp < 2; jp++) ffma2(acc[i][jp], a8[i], b2[jp]);
    }
}

__global__ __launch_bounds__(256, 2) void gemm_nn_db(
    const float* __restrict__ A, int lda, long long sAz,
    const float* __restrict__ Bm, int ldb, long long sBb, long long sBh,
    float* __restrict__ C, int ldc, long long sCb, long long sCh,
    int K)
{
    const int z = blockIdx.z, zb = z >> 4, zh = z & 15;
    A  += (long long)z * sAz;
    Bm += (long long)zb * sBb + (long long)zh * sBh;
    C  += (long long)zb * sCb + (long long)zh * sCh;

    __shared__ float As[2][16][256];   // 32 KB (P duplicated)
    __shared__ float Bs[2][16][64];    // 8 KB

    const int tid = threadIdx.x;
    const int tx = tid & 15, ty = tid >> 4;
    const int bm = blockIdx.y * 128;
    const int lm = tid >> 1, lk = (tid & 1) * 8;
    const int vk = tid >> 4, vn = (tid & 15) * 4;   // V-tile loader: 16x16 threads

    const float* Aptr = A + (long long)(bm + lm) * lda + lk;

    u64 acc[8][2];
#pragma unroll
    for (int i = 0; i < 8; i++) { acc[i][0] = 0ULL; acc[i][1] = 0ULL; }

    // tile 0
    {
        float4 a0 = *(const float4*)(Aptr);
        float4 a1 = *(const float4*)(Aptr + 4);
        float4 bv = *(const float4*)(Bm + (long long)vk * ldb + vn);
        float av[8] = {a0.x,a0.y,a0.z,a0.w,a1.x,a1.y,a1.z,a1.w};
#pragma unroll
        for (int j = 0; j < 8; j++)
            *(u64*)&As[0][lk + j][2 * lm] = pack2(av[j], av[j]);
        *(float4*)&Bs[0][vk][vn] = bv;
    }
    __syncthreads();

    int buf = 0;
    for (int k0 = 16; k0 < K; k0 += 16) {
        float4 a0 = *(const float4*)(Aptr + k0);
        float4 a1 = *(const float4*)(Aptr + k0 + 4);
        float4 bv = *(const float4*)(Bm + (long long)(k0 + vk) * ldb + vn);

        nn_compute(As[buf], Bs[buf], ty, tx, acc);

        {
            float av[8] = {a0.x,a0.y,a0.z,a0.w,a1.x,a1.y,a1.z,a1.w};
            const int nb = buf ^ 1;
#pragma unroll
            for (int j = 0; j < 8; j++)
                *(u64*)&As[nb][lk + j][2 * lm] = pack2(av[j], av[j]);
            *(float4*)&Bs[nb][vk][vn] = bv;
        }
        __syncthreads();
        buf ^= 1;
    }
    nn_compute(As[buf], Bs[buf], ty, tx, acc);

#pragma unroll
    for (int i = 0; i < 8; i++) {
        float* crow = C + (long long)(bm + ty * 8 + i) * ldc + tx * 4;
#pragma unroll
        for (int jp = 0; jp < 2; jp++) {
            float2 v = unpack2(acc[i][jp]);
            crow[2 * jp]     = v.x;
            crow[2 * jp + 1] = v.y;
        }
    }
}

// ---------------------------------------------------------------------------
// Softmax over rows of P (in place), adds broadcast mask. float4 I/O.
// One 256-thread block per row of 2048 floats. Row id = ((b*H+h)*S + q).
// ---------------------------------------------------------------------------
__global__ __launch_bounds__(256) void softmax_kernel(
    float* __restrict__ P, const float* __restrict__ mask)
{
    const long long row = blockIdx.x;
    const int q = (int)(row & (Sq - 1));
    const int b = (int)(row >> 15);
    float4* p = (float4*)(P + row * Sq);
    const float4* m = (const float4*)(mask + ((long long)b * Sq + q) * Sq);

    const int t = threadIdx.x;
    const int lane = t & 31, wid = t >> 5;
    __shared__ float red[8];

    float4 v0 = p[t], v1 = p[t + 256];
    float4 m0 = m[t], m1 = m[t + 256];
    v0.x += m0.x; v0.y += m0.y; v0.z += m0.z; v0.w += m0.w;
    v1.x += m1.x; v1.y += m1.y; v1.z += m1.z; v1.w += m1.w;

    float mx = fmaxf(fmaxf(fmaxf(v0.x, v0.y), fmaxf(v0.z, v0.w)),
                     fmaxf(fmaxf(v1.x, v1.y), fmaxf(v1.z, v1.w)));
#pragma unroll
    for (int o = 16; o > 0; o >>= 1) mx = fmaxf(mx, __shfl_xor_sync(0xffffffffu, mx, o));
    if (lane == 0) red[wid] = mx;
    __syncthreads();
    mx = red[0];
#pragma unroll
    for (int w = 1; w < 8; w++) mx = fmaxf(mx, red[w]);
    __syncthreads();

    v0.x = __expf(v0.x - mx); v0.y = __expf(v0.y - mx);
    v0.z = __expf(v0.z - mx); v0.w = __expf(v0.w - mx);
    v1.x = __expf(v1.x - mx); v1.y = __expf(v1.y - mx);
    v1.z = __expf(v1.z - mx); v1.w = __expf(v1.w - mx);
    float s = v0.x + v0.y + v0.z + v0.w + v1.x + v1.y + v1.z + v1.w;
#pragma unroll
    for (int o = 16; o > 0; o >>= 1) s += __shfl_xor_sync(0xffffffffu, s, o);
    if (lane == 0) red[wid] = s;
    __syncthreads();
    s = red[0];
#pragma unroll
    for (int w = 1; w < 8; w++) s += red[w];

    const float inv = 1.0f / s;
    v0.x *= inv; v0.y *= inv; v0.z *= inv; v0.w *= inv;
    v1.x *= inv; v1.y *= inv; v1.z *= inv; v1.w *= inv;
    p[t] = v0; p[t + 256] = v1;
}

// ---------------------------------------------------------------------------
// Host launcher
// ---------------------------------------------------------------------------
extern "C" void kernel_launch(void* const* d_in, const int* in_sizes, int n_in,
                              void* d_out, int out_size)
{
    const float* q    = (const float*)d_in[0];
    const float* k    = (const float*)d_in[1];
    const float* v    = (const float*)d_in[2];
    const float* mask = (const float*)d_in[3];
    const float* Wq   = (const float*)d_in[4];
    const float* Wk   = (const float*)d_in[5];
    const float* Wv   = (const float*)d_in[6];
    const float* Wo   = (const float*)d_in[7];
    float* out = (float*)d_out;

    void *pQ, *pK, *pV, *pO;
    cudaGetSymbolAddress(&pQ, g_Q);
    cudaGetSymbolAddress(&pK, g_K);
    cudaGetSymbolAddress(&pV, g_V);
    cudaGetSymbolAddress(&pO, g_O);

    float* Qb = (float*)pQ;
    float* Kb = (float*)pK;
    float* Vb = (float*)pV;
    float* Ob = (float*)pO;

    float* P = out + OUT_ATTN;      // attn_weights region of d_out

    const dim3 blk(256);

    // 1) Projections: X @ W^T (M=4096, N=1024, K=1024)
    {
        dim3 grid(Dm / 128, TOK / 128, 1);
        gemm_nt_db<<<grid, blk>>>(q, Dm, 0, 0, Wq, Dm, 0, 0,
                                  Qb, Dm, 0, 0, Dm, 1.0f);
        gemm_nt_db<<<grid, blk>>>(k, Dm, 0, 0, Wk, Dm, 0, 0,
                                  Kb, Dm, 0, 0, Dm, 1.0f);
        gemm_nt_db<<<grid, blk>>>(v, Dm, 0, 0, Wv, Dm, 0, 0,
                                  Vb, Dm, 0, 0, Dm, 1.0f);
    }

    // 2) Scores: P = (Q_h @ K_h^T) / 8. M=N=2048, K=64, batched over 32 heads.
    {
        dim3 grid(Sq / 128, Sq / 128, BH);
        gemm_nt_db<<<grid, blk>>>(
            Qb, Dm, (long long)Sq * Dm, HD,
            Kb, Dm, (long long)Sq * Dm, HD,
            P,  Sq, (long long)Hn * Sq * Sq, (long long)Sq * Sq,
            HD, 0.125f);
    }

    // 3) Softmax (in place, adds mask)
    softmax_kernel<<<BH * Sq, blk>>>(P, mask);

    // 4) O_h = P_h @ V_h into merged-head layout
    {
        dim3 grid(1, Sq / 128, BH);
        gemm_nn_db<<<grid, blk>>>(
            P,  Sq, (long long)Sq * Sq,
            Vb, Dm, (long long)Sq * Dm, HD,
            Ob, Dm, (long long)Sq * Dm, HD,
            Sq);
    }

    // 5) attn_output = O @ Wo^T
    {
        dim3 grid(Dm / 128, TOK / 128, 1);
        gemm_nt_db<<<grid, blk>>>(Ob, Dm, 0, 0, Wo, Dm, 0, 0,
                                  out, Dm, 0, 0, Dm, 1.0f);
    }
}